// round 1
// baseline (speedup 1.0000x reference)
#include <cuda_runtime.h>
#include <math.h>
#include <stdint.h>

// ======================= problem dimensions =======================
constexpr int  NB    = 64;            // batch
constexpr int  S     = 196;           // patches (14x14)
constexpr int  D     = 256;           // hidden dim
constexpr long ROWS  = (long)NB * S;  // 12544

// ======================= scratch layout (floats) =======================
constexpr long SZ_COL = ROWS * 2304;          // im2col buffer (max K = 256*9)
constexpr long SZ_BSD = ROWS * 256;           // [B,S,256] tensors

constexpr long O_COL  = 0;
constexpr long O_Y    = O_COL  + SZ_COL;
constexpr long O_SC   = O_Y    + SZ_BSD;                  // scores [B,196,196]
constexpr long O_REA  = O_SC   + (long)NB * S * S;
constexpr long O_RE2  = O_REA  + SZ_BSD;
constexpr long O_PRE1 = O_RE2  + SZ_BSD;
constexpr long O_OUT  = O_PRE1 + SZ_BSD;
constexpr long O_R1   = O_OUT  + SZ_BSD;
constexpr long O_R2   = O_R1   + ROWS * 128;
constexpr long O_R3   = O_R2   + ROWS * 64;
constexpr long O_R3T  = O_R3   + ROWS * 32;
constexpr long O_PART = O_R3T  + ROWS * 32;               // split-K partials
constexpr long SZ_PART = 2097152;                          // >= 32*64*1024 and 8*64*3136
constexpr long O_RFC  = O_PART + SZ_PART;
constexpr long O_H1   = O_RFC  + 64L * 3136;
constexpr long O_REX  = O_H1   + SZ_BSD;
constexpr long O_OUT1 = O_REX  + SZ_BSD;
constexpr long O_OT   = O_OUT1 + SZ_BSD;                  // bn2 out, [b][c][s]
constexpr long O_OFC  = O_OT   + SZ_BSD;
constexpr long O_BS1  = O_OFC  + 64L * 1024;              // bn partial sums [64][256]
constexpr long O_BS2  = O_BS1  + 64L * 256;
constexpr long O_MEAN = O_BS2  + 64L * 256;
constexpr long O_ISTD = O_MEAN + 256;
constexpr long O_SCAL = O_ISTD + 256;                     // gate scale [64]
constexpr long O_RC1P = O_SCAL + 64;
constexpr long O_RC2P = O_RC1P + 128L * 2304;
constexpr long O_RC3P = O_RC2P + 64L * 1152;
constexpr long O_EW1P = O_RC3P + 32L * 576;
constexpr long O_EW2P = O_EW1P + 8L * 256 * 2304;
constexpr long O_END  = O_EW2P + 8L * 256 * 2304;

__device__ float g_scratch[O_END];
__device__ int   g_pos[64];

// ======================= device helpers =======================
__device__ __forceinline__ float geluf(float v) {
    return 0.5f * v * (1.0f + erff(v * 0.70710678118654752440f));
}
__device__ __forceinline__ unsigned long long pk2(float a, float b) {
    unsigned long long r;
    asm("mov.b64 %0, {%1, %2};" : "=l"(r) : "f"(a), "f"(b));
    return r;
}
__device__ __forceinline__ void fma2(unsigned long long& d,
                                     unsigned long long a, unsigned long long b) {
    asm("fma.rn.f32x2 %0, %1, %2, %0;" : "+l"(d) : "l"(a), "l"(b));
}
__device__ __forceinline__ float2 up2(unsigned long long v) {
    float a, b;
    asm("mov.b64 {%0, %1}, %2;" : "=f"(a), "=f"(b) : "l"(v));
    return make_float2(a, b);
}

// ======================= generic fp32 GEMM =======================
// C[M,N] = act(alpha * A[M,K] @ op(B) + bias) * zscale
//   B_NK=true : B is [N,K] row-major (weights / Y^T)
//   B_NK=false: B is [K,N] row-major
//   SPLIT=true: blockIdx.z = k-split, writes partials to C + z*M*N (no bias/act)
//   else      : blockIdx.z = batch; B (and bias) offset by bIdx[z] if given.
template<bool B_NK, bool SPLIT>
__global__ __launch_bounds__(256) void k_gemm(
    const float* __restrict__ A, const float* __restrict__ Bm, float* __restrict__ C,
    int M, int N, int K,
    long sA, long sB, long sC,
    const int* __restrict__ bIdx,
    const float* __restrict__ bias, long sBias,
    const float* __restrict__ zscale,
    float alpha, int act, int nsplit)
{
    __shared__ __align__(16) float As[16][68];
    __shared__ __align__(16) float Bs[16][68];

    const int z = blockIdx.z;
    int kBeg = 0, kEnd = K;
    float zs = 1.0f;
    const float* biasP = nullptr;
    if (SPLIT) {
        int kc = (K + nsplit - 1) / nsplit;
        kBeg = z * kc;
        kEnd = min(K, kBeg + kc);
        C += (long)z * M * N;
    } else {
        A += (long)z * sA;
        int bi = bIdx ? bIdx[z] : z;
        Bm += (long)bi * sB;
        C += (long)z * sC;
        if (bias) biasP = bias + (long)bi * sBias;
        if (zscale) zs = zscale[z];
    }

    const int tid = threadIdx.x;
    const int m0 = blockIdx.y * 64;
    const int n0 = blockIdx.x * 64;
    const int tr = tid >> 4;     // 0..15
    const int tc = tid & 15;     // 0..15

    unsigned long long acc[4][2];
#pragma unroll
    for (int i = 0; i < 4; i++) { acc[i][0] = 0ULL; acc[i][1] = 0ULL; }

    for (int k0 = kBeg; k0 < kEnd; k0 += 16) {
        // load A tile (64x16) -> As[k][m]
#pragma unroll
        for (int i = 0; i < 4; i++) {
            int f  = tid + i * 256;
            int m  = f >> 4;
            int kk = f & 15;
            int gm = m0 + m, gk = k0 + kk;
            As[kk][m] = (gm < M && gk < kEnd) ? A[(long)gm * K + gk] : 0.0f;
        }
        // load B tile (64x16) -> Bs[k][n]
#pragma unroll
        for (int i = 0; i < 4; i++) {
            int f = tid + i * 256;
            if (B_NK) {
                int n  = f >> 4;
                int kk = f & 15;
                int gn = n0 + n, gk = k0 + kk;
                Bs[kk][n] = (gn < N && gk < kEnd) ? Bm[(long)gn * K + gk] : 0.0f;
            } else {
                int n  = f & 63;
                int kk = f >> 6;
                int gn = n0 + n, gk = k0 + kk;
                Bs[kk][n] = (gn < N && gk < kEnd) ? Bm[(long)gk * N + gn] : 0.0f;
            }
        }
        __syncthreads();
#pragma unroll
        for (int kk = 0; kk < 16; kk++) {
            float4 av = *(const float4*)&As[kk][tr * 4];
            ulonglong2 bp = *(const ulonglong2*)&Bs[kk][tc * 4];
            unsigned long long a0 = pk2(av.x, av.x);
            unsigned long long a1 = pk2(av.y, av.y);
            unsigned long long a2 = pk2(av.z, av.z);
            unsigned long long a3 = pk2(av.w, av.w);
            fma2(acc[0][0], a0, bp.x); fma2(acc[0][1], a0, bp.y);
            fma2(acc[1][0], a1, bp.x); fma2(acc[1][1], a1, bp.y);
            fma2(acc[2][0], a2, bp.x); fma2(acc[2][1], a2, bp.y);
            fma2(acc[3][0], a3, bp.x); fma2(acc[3][1], a3, bp.y);
        }
        __syncthreads();
    }

    // epilogue
#pragma unroll
    for (int i = 0; i < 4; i++) {
        int gm = m0 + tr * 4 + i;
        if (gm >= M) continue;
#pragma unroll
        for (int jp = 0; jp < 2; jp++) {
            float2 v = up2(acc[i][jp]);
#pragma unroll
            for (int e = 0; e < 2; e++) {
                int gn = n0 + tc * 4 + jp * 2 + e;
                if (gn >= N) continue;
                float val = (e ? v.y : v.x) * alpha;
                if (biasP) val += biasP[gn];
                if (act == 1) val = geluf(val);
                val *= zs;
                C[(long)gm * N + gn] = val;
            }
        }
    }
}

// ======================= small kernels =======================
__global__ void k_permute3x3(const float* __restrict__ src, float* __restrict__ dst,
                             int Nout, int Cin) {
    long total = (long)Nout * Cin * 9;
    for (long i = blockIdx.x * (long)blockDim.x + threadIdx.x; i < total;
         i += (long)gridDim.x * blockDim.x) {
        int n = (int)(i / (Cin * 9));
        int r = (int)(i % (Cin * 9));
        int off = r / Cin, c = r % Cin;
        dst[i] = src[((long)n * Cin + c) * 9 + off];
    }
}

__global__ void k_im2col_patch(const float* __restrict__ x, float* __restrict__ dst) {
    long total = ROWS * 768;
    for (long i = blockIdx.x * (long)blockDim.x + threadIdx.x; i < total;
         i += (long)gridDim.x * blockDim.x) {
        int row = (int)(i / 768), k = (int)(i % 768);
        int b = row / 196, s = row % 196;
        int ph = s / 14, pw = s % 14;
        int c = k >> 8, r = k & 255, ii = r >> 4, jj = r & 15;
        dst[i] = x[(((long)(b * 3 + c) * 224) + ph * 16 + ii) * 224 + pw * 16 + jj];
    }
}

__global__ void k_im2col3(const float* __restrict__ src, float* __restrict__ dst, int Cin) {
    int K = 9 * Cin;
    long total = ROWS * K;
    for (long i = blockIdx.x * (long)blockDim.x + threadIdx.x; i < total;
         i += (long)gridDim.x * blockDim.x) {
        int row = (int)(i / K), k = (int)(i % K);
        int off = k / Cin, c = k % Cin;
        int b = row / 196, s = row % 196;
        int yy = s / 14, xx = s % 14;
        int sy = yy + off / 3 - 1, sx = xx + off % 3 - 1;
        float v = 0.0f;
        if ((unsigned)sy < 14u && (unsigned)sx < 14u)
            v = src[((long)(b * 196 + sy * 14 + sx)) * Cin + c];
        dst[i] = v;
    }
}

__global__ void k_addpos(float* __restrict__ y, const float* __restrict__ pos) {
    long total = ROWS * 256;
    for (long i = blockIdx.x * (long)blockDim.x + threadIdx.x; i < total;
         i += (long)gridDim.x * blockDim.x)
        y[i] += pos[i % (196 * 256)];
}

__global__ void k_add(float* __restrict__ dst, const float* __restrict__ a,
                      const float* __restrict__ b, long n) {
    for (long i = blockIdx.x * (long)blockDim.x + threadIdx.x; i < n;
         i += (long)gridDim.x * blockDim.x)
        dst[i] = a[i] + b[i];
}

__global__ void k_softmax(float* __restrict__ sc) {
    long row = blockIdx.x;                 // 12544 rows of 196
    float* p = sc + row * 196;
    int t = threadIdx.x;                   // 256 threads
    __shared__ float red[256];
    float v = (t < 196) ? p[t] : -3.4e38f;
    red[t] = v;
    __syncthreads();
    for (int s = 128; s > 0; s >>= 1) { if (t < s) red[t] = fmaxf(red[t], red[t + s]); __syncthreads(); }
    float mx = red[0];
    __syncthreads();
    float ex = (t < 196) ? expf(v - mx) : 0.0f;
    red[t] = ex;
    __syncthreads();
    for (int s = 128; s > 0; s >>= 1) { if (t < s) red[t] += red[t + s]; __syncthreads(); }
    float inv = 1.0f / red[0];
    if (t < 196) p[t] = ex * inv;
}

// deterministic BN stats: 64 chunks x 196 rows, thread = channel
__global__ void k_bnstat(const float* __restrict__ x, float* __restrict__ psum,
                         float* __restrict__ psq) {
    int c = threadIdx.x;       // 0..255
    int ch = blockIdx.x;       // 0..63
    float s = 0.0f, q = 0.0f;
    long r0 = (long)ch * 196;
    for (int r = 0; r < 196; r++) {
        float v = x[(r0 + r) * 256 + c];
        s += v;
        q += v * v;
    }
    psum[ch * 256 + c] = s;
    psq[ch * 256 + c]  = q;
}
__global__ void k_bnfin(const float* __restrict__ psum, const float* __restrict__ psq,
                        float* __restrict__ mean, float* __restrict__ istd) {
    int c = threadIdx.x;
    float s = 0.0f, q = 0.0f;
    for (int i = 0; i < 64; i++) { s += psum[i * 256 + c]; q += psq[i * 256 + c]; }
    float m = s / 12544.0f;
    float var = q / 12544.0f - m * m;
    mean[c] = m;
    istd[c] = rsqrtf(var + 1e-5f);
}
__global__ void k_bnnorm(const float* __restrict__ x, float* __restrict__ out,
                         const float* __restrict__ mean, const float* __restrict__ istd,
                         const float* __restrict__ g, const float* __restrict__ b,
                         int transposed) {
    long total = ROWS * 256;
    for (long i = blockIdx.x * (long)blockDim.x + threadIdx.x; i < total;
         i += (long)gridDim.x * blockDim.x) {
        int c = (int)(i & 255);
        long row = i >> 8;
        float v = (x[i] - mean[c]) * istd[c] * g[c] + b[c];
        if (!transposed) {
            out[i] = v;
        } else {
            int bb = (int)(row / 196), ss = (int)(row % 196);
            out[(long)bb * 50176 + c * 196 + ss] = v;
        }
    }
}

__global__ void k_tr32(const float* __restrict__ src, float* __restrict__ dst) {
    long total = ROWS * 32;
    for (long i = blockIdx.x * (long)blockDim.x + threadIdx.x; i < total;
         i += (long)gridDim.x * blockDim.x) {
        int b = (int)(i / 6272);
        int r = (int)(i % 6272);
        int c = r / 196, s = r % 196;
        dst[i] = src[((long)(b * 196 + s)) * 32 + c];
    }
}

__global__ void k_reduce(const float* __restrict__ part, float* __restrict__ out,
                         int M, int N, int nsplit, const float* __restrict__ bias, int act) {
    long total = (long)M * N;
    for (long i = blockIdx.x * (long)blockDim.x + threadIdx.x; i < total;
         i += (long)gridDim.x * blockDim.x) {
        int n = (int)(i % N);
        float s = 0.0f;
        for (int p = 0; p < nsplit; p++) s += part[(long)p * total + i];
        if (bias) s += bias[n];
        if (act) s = geluf(s);
        out[i] = s;
    }
}

// rd2 (8 experts) + argmax + gate, one block per sample
__global__ void k_rd2(const float* __restrict__ rfc, const float* __restrict__ w,
                      const float* __restrict__ b, int* __restrict__ pos,
                      float* __restrict__ scale) {
    int bb = blockIdx.x;
    int t = threadIdx.x;
    int e = t >> 5, lane = t & 31;
    const float* xr = rfc + (long)bb * 3136;
    const float* wr = w + (long)e * 3136;
    float s = 0.0f;
    for (int k = lane; k < 3136; k += 32) s += xr[k] * wr[k];
    for (int o = 16; o > 0; o >>= 1) s += __shfl_down_sync(0xffffffffu, s, o);
    __shared__ float lg[8];
    if (lane == 0) lg[e] = s + b[e];
    __syncthreads();
    if (t == 0) {
        int best = 0;
        float bv = lg[0];
        for (int e2 = 1; e2 < 8; e2++)
            if (lg[e2] > bv) { bv = lg[e2]; best = e2; }
        pos[bb] = best;
        scale[bb] = bv;
    }
}

// ======================= host-side launchers =======================
static inline int GS(long n) { return (int)((n + 255) / 256); }

static void gemm_nk(const float* A, const float* B, float* C, int M, int N, int K,
                    int Z, long sA, long sB, long sC,
                    const int* bIdx, const float* bias, long sBias,
                    const float* zscale, float alpha, int act) {
    dim3 g((N + 63) / 64, (M + 63) / 64, Z);
    k_gemm<true, false><<<g, 256>>>(A, B, C, M, N, K, sA, sB, sC,
                                    bIdx, bias, sBias, zscale, alpha, act, 1);
}
static void gemm_kn(const float* A, const float* B, float* C, int M, int N, int K,
                    int Z, long sA, long sB, long sC) {
    dim3 g((N + 63) / 64, (M + 63) / 64, Z);
    k_gemm<false, false><<<g, 256>>>(A, B, C, M, N, K, sA, sB, sC,
                                     nullptr, nullptr, 0, nullptr, 1.0f, 0, 1);
}
static void gemm_nk_split(const float* A, const float* B, float* part,
                          int M, int N, int K, int nsplit) {
    dim3 g((N + 63) / 64, (M + 63) / 64, nsplit);
    k_gemm<true, true><<<g, 256>>>(A, B, part, M, N, K, 0, 0, 0,
                                   nullptr, nullptr, 0, nullptr, 1.0f, 0, nsplit);
}

extern "C" void kernel_launch(void* const* d_in, const int* in_sizes, int n_in,
                              void* d_out, int out_size) {
    const float* x       = (const float*)d_in[0];
    const float* patch_w = (const float*)d_in[1];
    const float* patch_b = (const float*)d_in[2];
    const float* pos_emb = (const float*)d_in[3];
    const float* wo_w    = (const float*)d_in[4];
    const float* wo_b    = (const float*)d_in[5];
    const float* bn1_g   = (const float*)d_in[6];
    const float* bn1_b   = (const float*)d_in[7];
    const float* rc1_w   = (const float*)d_in[8];
    const float* rc1_b   = (const float*)d_in[9];
    const float* rc2_w   = (const float*)d_in[10];
    const float* rc2_b   = (const float*)d_in[11];
    const float* rc3_w   = (const float*)d_in[12];
    const float* rc3_b   = (const float*)d_in[13];
    const float* rd1_w   = (const float*)d_in[14];
    const float* rd1_b   = (const float*)d_in[15];
    const float* rd2_w   = (const float*)d_in[16];
    const float* rd2_b   = (const float*)d_in[17];
    const float* exp_w1  = (const float*)d_in[18];
    const float* exp_b1  = (const float*)d_in[19];
    const float* exp_w2  = (const float*)d_in[20];
    const float* exp_b2  = (const float*)d_in[21];
    const float* shard_w = (const float*)d_in[22];
    const float* shard_b = (const float*)d_in[23];
    const float* bn2_g   = (const float*)d_in[24];
    const float* bn2_b   = (const float*)d_in[25];
    const float* od1_w   = (const float*)d_in[26];
    const float* od1_b   = (const float*)d_in[27];
    const float* od2_w   = (const float*)d_in[28];
    const float* od2_b   = (const float*)d_in[29];

    float* Sb = nullptr;
    cudaGetSymbolAddress((void**)&Sb, g_scratch);
    int* posP = nullptr;
    cudaGetSymbolAddress((void**)&posP, g_pos);

    float* col   = Sb + O_COL;
    float* Y     = Sb + O_Y;
    float* sc    = Sb + O_SC;
    float* reA   = Sb + O_REA;
    float* re2   = Sb + O_RE2;
    float* pre1  = Sb + O_PRE1;
    float* outb  = Sb + O_OUT;
    float* r1    = Sb + O_R1;
    float* r2    = Sb + O_R2;
    float* r3    = Sb + O_R3;
    float* r3t   = Sb + O_R3T;
    float* part  = Sb + O_PART;
    float* rfc   = Sb + O_RFC;
    float* h1    = Sb + O_H1;
    float* rexp  = Sb + O_REX;
    float* out1  = Sb + O_OUT1;
    float* ot    = Sb + O_OT;
    float* ofc   = Sb + O_OFC;
    float* bs1   = Sb + O_BS1;
    float* bs2   = Sb + O_BS2;
    float* meanp = Sb + O_MEAN;
    float* istdp = Sb + O_ISTD;
    float* scalp = Sb + O_SCAL;
    float* rc1p  = Sb + O_RC1P;
    float* rc2p  = Sb + O_RC2P;
    float* rc3p  = Sb + O_RC3P;
    float* ew1p  = Sb + O_EW1P;
    float* ew2p  = Sb + O_EW2P;

    const float inv14 = 1.0f / sqrtf(14.0f);

    // ---- weight permutes: [Cout][Cin][3][3] -> [Cout][off*Cin + c] ----
    k_permute3x3<<<GS(128L * 2304), 256>>>(rc1_w, rc1p, 128, 256);
    k_permute3x3<<<GS(64L * 1152),  256>>>(rc2_w, rc2p, 64, 128);
    k_permute3x3<<<GS(32L * 576),   256>>>(rc3_w, rc3p, 32, 64);
    k_permute3x3<<<GS(2048L * 2304), 256>>>(exp_w1, ew1p, 2048, 256);
    k_permute3x3<<<GS(2048L * 2304), 256>>>(exp_w2, ew2p, 2048, 256);

    // ---- patch embedding -> Y [B,S,D], + pos_emb ----
    k_im2col_patch<<<GS(ROWS * 768), 256>>>(x, col);
    gemm_nk(col, patch_w, Y, 12544, 256, 768, 1, 0, 0, 0,
            nullptr, patch_b, 0, nullptr, 1.0f, 0);
    k_addpos<<<GS(ROWS * 256), 256>>>(Y, pos_emb);

    // ---- attention ----
    gemm_nk(Y, Y, sc, 196, 196, 256, NB, (long)S * D, (long)S * D, (long)S * S,
            nullptr, nullptr, 0, nullptr, inv14, 0);
    k_softmax<<<12544, 256>>>(sc);
    gemm_kn(sc, Y, reA, 196, 256, 196, NB, (long)S * S, (long)S * D, (long)S * D);
    gemm_nk(reA, wo_w, re2, 12544, 256, 256, 1, 0, 0, 0,
            nullptr, wo_b, 0, nullptr, 1.0f, 0);
    k_add<<<GS(ROWS * 256), 256>>>(pre1, Y, re2, ROWS * 256);

    // ---- bn1 -> out ----
    k_bnstat<<<64, 256>>>(pre1, bs1, bs2);
    k_bnfin<<<1, 256>>>(bs1, bs2, meanp, istdp);
    k_bnnorm<<<GS(ROWS * 256), 256>>>(pre1, outb, meanp, istdp, bn1_g, bn1_b, 0);

    // ---- router convs ----
    k_im2col3<<<GS(ROWS * 2304), 256>>>(outb, col, 256);
    gemm_nk(col, rc1p, r1, 12544, 128, 2304, 1, 0, 0, 0,
            nullptr, rc1_b, 0, nullptr, 1.0f, 1);
    k_im2col3<<<GS(ROWS * 1152), 256>>>(r1, col, 128);
    gemm_nk(col, rc2p, r2, 12544, 64, 1152, 1, 0, 0, 0,
            nullptr, rc2_b, 0, nullptr, 1.0f, 1);
    k_im2col3<<<GS(ROWS * 576), 256>>>(r2, col, 64);
    gemm_nk(col, rc3p, r3, 12544, 32, 576, 1, 0, 0, 0,
            nullptr, rc3_b, 0, nullptr, 1.0f, 1);
    k_tr32<<<GS(ROWS * 32), 256>>>(r3, r3t);

    // ---- router dense ----
    gemm_nk_split(r3t, rd1_w, part, 64, 3136, 6272, 8);
    k_reduce<<<GS(64L * 3136), 256>>>(part, rfc, 64, 3136, 8, rd1_b, 1);
    k_rd2<<<64, 256>>>(rfc, rd2_w, rd2_b, posP, scalp);

    // ---- experts (per-sample weight via posP) ----
    k_im2col3<<<GS(ROWS * 2304), 256>>>(re2, col, 256);
    gemm_nk(col, ew1p, h1, 196, 256, 2304, NB,
            (long)196 * 2304, (long)256 * 2304, (long)196 * 256,
            posP, exp_b1, 256, nullptr, 1.0f, 1);
    k_im2col3<<<GS(ROWS * 2304), 256>>>(h1, col, 256);
    gemm_nk(col, ew2p, rexp, 196, 256, 2304, NB,
            (long)196 * 2304, (long)256 * 2304, (long)196 * 256,
            posP, exp_b2, 256, scalp, 1.0f, 1);

    // ---- shard shortcut + sum + bn2 (transposed write [b][c][s]) ----
    gemm_nk(outb, shard_w, out1, 12544, 256, 256, 1, 0, 0, 0,
            nullptr, shard_b, 0, nullptr, 1.0f, 0);
    k_add<<<GS(ROWS * 256), 256>>>(rexp, rexp, out1, ROWS * 256);
    k_bnstat<<<64, 256>>>(rexp, bs1, bs2);
    k_bnfin<<<1, 256>>>(bs1, bs2, meanp, istdp);
    k_bnnorm<<<GS(ROWS * 256), 256>>>(rexp, ot, meanp, istdp, bn2_g, bn2_b, 1);

    // ---- output head ----
    gemm_nk_split(ot, od1_w, part, 64, 1024, 50176, 32);
    k_reduce<<<GS(64L * 1024), 256>>>(part, ofc, 64, 1024, 32, od1_b, 1);
    gemm_nk_split(ofc, od2_w, part, 64, 1000, 1024, 8);
    k_reduce<<<GS(64L * 1000), 256>>>(part, (float*)d_out, 64, 1000, 8, od2_b, 0);
}